// round 2
// baseline (speedup 1.0000x reference)
#include <cuda_runtime.h>

// SNN elementwise state update, B*D = 4096*4096 fp32. Pure streaming, HBM-bound.
// Inputs (metadata order): total_input_current, v, x, j, ref_count
// Outputs packed in d_out: [v | s | x | j | ref_count], each B*D floats.
//
// R2: 2 quads/thread (10 front-batched LDG.128), streaming cache hints
// (__ldcs / __stcs) since every line is touched exactly once.

__device__ __forceinline__ void snn_update(float I, float& v, float& x,
                                           float& j, float& rc, float& s) {
    const float dt       = 0.5f;
    const float dt_tauj  = 0.0625f;   // 0.5/8
    const float kappa_j  = 0.2f;
    const float dt_taum  = 0.05f;     // 0.5/10
    const float gamma_m  = 0.1f;
    const float R_m      = 5.0f;
    const float thresh   = 1.0f;
    const float t_ref    = 2.0f;
    const float inv_ttr  = 0.05f;     // 1/20

    rc = fmaxf(rc - dt, 0.0f);
    j = j + dt_tauj * (-kappa_j * j + I);
    float is_ref = (rc > 0.0f) ? 1.0f : 0.0f;
    v = v + (1.0f - is_ref) * dt_taum * (-gamma_m * v + R_m * j);
    float spikes = (v > thresh) ? 1.0f : 0.0f;
    s = spikes;
    v = v * (1.0f - spikes);
    rc = (spikes > 0.0f) ? t_ref : rc;
    x = x - x * inv_ttr + spikes;
}

__device__ __forceinline__ void snn_update4(const float4& I, float4& v, float4& x,
                                            float4& j, float4& rc, float4& s) {
    snn_update(I.x, v.x, x.x, j.x, rc.x, s.x);
    snn_update(I.y, v.y, x.y, j.y, rc.y, s.y);
    snn_update(I.z, v.z, x.z, j.z, rc.z, s.z);
    snn_update(I.w, v.w, x.w, j.w, rc.w, s.w);
}

__global__ void __launch_bounds__(256)
snn_kernel(const float4* __restrict__ in_I,
           const float4* __restrict__ in_v,
           const float4* __restrict__ in_x,
           const float4* __restrict__ in_j,
           const float4* __restrict__ in_rc,
           float4* __restrict__ out_v,
           float4* __restrict__ out_s,
           float4* __restrict__ out_x,
           float4* __restrict__ out_j,
           float4* __restrict__ out_rc,
           int n4) {
    // Two quads per thread, coalesced within the block:
    // block covers [base, base + 2*blockDim) quads.
    int base = blockIdx.x * (blockDim.x * 2) + threadIdx.x;
    int i0 = base;
    int i1 = base + blockDim.x;

    if (i1 < n4) {
        // Front-batch all 10 loads (streaming / evict-first).
        float4 I0  = __ldcs(in_I  + i0);
        float4 v0  = __ldcs(in_v  + i0);
        float4 x0  = __ldcs(in_x  + i0);
        float4 j0  = __ldcs(in_j  + i0);
        float4 rc0 = __ldcs(in_rc + i0);
        float4 I1  = __ldcs(in_I  + i1);
        float4 v1  = __ldcs(in_v  + i1);
        float4 x1  = __ldcs(in_x  + i1);
        float4 j1  = __ldcs(in_j  + i1);
        float4 rc1 = __ldcs(in_rc + i1);

        float4 s0, s1;
        snn_update4(I0, v0, x0, j0, rc0, s0);
        snn_update4(I1, v1, x1, j1, rc1, s1);

        __stcs(out_v  + i0, v0);   __stcs(out_v  + i1, v1);
        __stcs(out_s  + i0, s0);   __stcs(out_s  + i1, s1);
        __stcs(out_x  + i0, x0);   __stcs(out_x  + i1, x1);
        __stcs(out_j  + i0, j0);   __stcs(out_j  + i1, j1);
        __stcs(out_rc + i0, rc0);  __stcs(out_rc + i1, rc1);
    } else {
        // Tail path (never taken for n4 = 4M with exact grid, kept for safety).
        for (int i = i0; i < n4; i += blockDim.x) {
            float4 I  = __ldcs(in_I  + i);
            float4 v  = __ldcs(in_v  + i);
            float4 x  = __ldcs(in_x  + i);
            float4 j  = __ldcs(in_j  + i);
            float4 rc = __ldcs(in_rc + i);
            float4 s;
            snn_update4(I, v, x, j, rc, s);
            __stcs(out_v  + i, v);
            __stcs(out_s  + i, s);
            __stcs(out_x  + i, x);
            __stcs(out_j  + i, j);
            __stcs(out_rc + i, rc);
        }
    }
}

extern "C" void kernel_launch(void* const* d_in, const int* in_sizes, int n_in,
                              void* d_out, int out_size) {
    const float4* I  = (const float4*)d_in[0];
    const float4* v  = (const float4*)d_in[1];
    const float4* x  = (const float4*)d_in[2];
    const float4* j  = (const float4*)d_in[3];
    const float4* rc = (const float4*)d_in[4];

    int n  = in_sizes[0];        // B*D elements (16,777,216)
    int n4 = n / 4;              // float4 quads (4,194,304)

    float* out = (float*)d_out;  // [v | s | x | j | ref_count]
    float4* ov  = (float4*)(out + 0L * n);
    float4* os  = (float4*)(out + 1L * n);
    float4* ox  = (float4*)(out + 2L * n);
    float4* oj  = (float4*)(out + 3L * n);
    float4* orc = (float4*)(out + 4L * n);

    int threads = 256;
    int per_block = threads * 2;
    int blocks = (n4 + per_block - 1) / per_block;   // 8192
    snn_kernel<<<blocks, threads>>>(I, v, x, j, rc, ov, os, ox, oj, orc, n4);
}